// round 14
// baseline (speedup 1.0000x reference)
#include <cuda_runtime.h>
#include <cuda_bf16.h>
#include <cstdint>

#define NX 8192
#define NF 8192
#define F_SIZE 512
#define OUT_SIZE 256
#define D_ATT 128
#define N_GRAPHS 16

// ---------------- scratch ----------------
__device__ int g_foff[N_GRAPHS + 1];
__device__ __nv_bfloat16 g_fh[NF * F_SIZE],  g_fl[NF * F_SIZE];
__device__ __nv_bfloat16 g_hh[NX * OUT_SIZE], g_hl[NX * OUT_SIZE];
__device__ __nv_bfloat16 g_qh[NX * D_ATT],   g_ql[NX * D_ATT];
__device__ __nv_bfloat16 g_kh[NF * D_ATT],   g_kl[NF * D_ATT];
__device__ __nv_bfloat16 g_vh[NF * OUT_SIZE], g_vl[NF * OUT_SIZE];
#define W_TOT (256 * 128 + 512 * 128 + 512 * 256)
__device__ __nv_bfloat16 g_wh[W_TOT], g_wl[W_TOT];
#define WOFF_Q 0
#define WOFF_K 32768
#define WOFF_V 98304

__global__ void offsets_kernel(const int* __restrict__ f_batch) {
    int g = threadIdx.x;
    if (g > N_GRAPHS) return;
    int lo = 0, hi = NF;
    while (lo < hi) { int mid = (lo + hi) >> 1; if (f_batch[mid] < g) lo = mid + 1; else hi = mid; }
    g_foff[g] = lo;
}

// ---------------- helpers ----------------
__device__ __forceinline__ unsigned su(const void* p) { return (unsigned)__cvta_generic_to_shared(p); }
__device__ __forceinline__ void cpa16(void* dst, const void* src) {
    asm volatile("cp.async.cg.shared.global [%0],[%1],16;\n" :: "r"(su(dst)), "l"(src));
}
#define CPA_COMMIT asm volatile("cp.async.commit_group;\n")
#define CPA_WAIT1  asm volatile("cp.async.wait_group 1;\n")
#define CPA_WAIT0  asm volatile("cp.async.wait_group 0;\n")

__device__ __forceinline__ void ldsm4(unsigned r[4], unsigned a) {
    asm volatile("ldmatrix.sync.aligned.m8n8.x4.shared.b16 {%0,%1,%2,%3},[%4];"
        : "=r"(r[0]), "=r"(r[1]), "=r"(r[2]), "=r"(r[3]) : "r"(a));
}
__device__ __forceinline__ void ldsm4t(unsigned r[4], unsigned a) {
    asm volatile("ldmatrix.sync.aligned.m8n8.x4.trans.shared.b16 {%0,%1,%2,%3},[%4];"
        : "=r"(r[0]), "=r"(r[1]), "=r"(r[2]), "=r"(r[3]) : "r"(a));
}
__device__ __forceinline__ void mma_bf(float d[4], const unsigned a[4], unsigned b0, unsigned b1) {
    asm volatile("mma.sync.aligned.m16n8k16.row.col.f32.bf16.bf16.f32 "
        "{%0,%1,%2,%3},{%4,%5,%6,%7},{%8,%9},{%0,%1,%2,%3};"
        : "+f"(d[0]), "+f"(d[1]), "+f"(d[2]), "+f"(d[3])
        : "r"(a[0]), "r"(a[1]), "r"(a[2]), "r"(a[3]), "r"(b0), "r"(b1));
}
__device__ __forceinline__ unsigned pk2(__nv_bfloat16 a, __nv_bfloat16 b) {
    __nv_bfloat162 t(a, b); return *reinterpret_cast<unsigned*>(&t);
}
__device__ __forceinline__ void split4(float4 v, uint2& hi, uint2& lo) {
    __nv_bfloat16 h0 = __float2bfloat16_rn(v.x), h1 = __float2bfloat16_rn(v.y);
    __nv_bfloat16 h2 = __float2bfloat16_rn(v.z), h3 = __float2bfloat16_rn(v.w);
    __nv_bfloat16 l0 = __float2bfloat16_rn(v.x - __bfloat162float(h0));
    __nv_bfloat16 l1 = __float2bfloat16_rn(v.y - __bfloat162float(h1));
    __nv_bfloat16 l2 = __float2bfloat16_rn(v.z - __bfloat162float(h2));
    __nv_bfloat16 l3 = __float2bfloat16_rn(v.w - __bfloat162float(h3));
    hi.x = pk2(h0, h1); hi.y = pk2(h2, h3);
    lo.x = pk2(l0, l1); lo.y = pk2(l2, l3);
}
__device__ __forceinline__ void split2w(float x, float y, unsigned& h, unsigned& l) {
    __nv_bfloat16 hx = __float2bfloat16_rn(x), hy = __float2bfloat16_rn(y);
    h = pk2(hx, hy);
    l = pk2(__float2bfloat16_rn(x - __bfloat162float(hx)),
            __float2bfloat16_rn(y - __bfloat162float(hy)));
}

// ---------------- fused fp32 -> bf16 hi/lo for all 5 inputs ----------------
#define SEG0 1048576
#define SEG1 (SEG0 + 524288)
#define SEG2 (SEG1 + 8192)
#define SEG3 (SEG2 + 16384)
#define SEG4 (SEG3 + 32768)
__global__ void split_all(const float4* __restrict__ f, const float4* __restrict__ h,
                          const float4* __restrict__ Wh, const float4* __restrict__ Wk,
                          const float4* __restrict__ Wv) {
    int i = blockIdx.x * blockDim.x + threadIdx.x;
    int s = gridDim.x * blockDim.x;
    for (; i < SEG4; i += s) {
        const float4* src; uint2 *dh, *dl; int li;
        if (i < SEG0)      { src = f;  li = i;        dh = (uint2*)g_fh; dl = (uint2*)g_fl; }
        else if (i < SEG1) { src = h;  li = i - SEG0; dh = (uint2*)g_hh; dl = (uint2*)g_hl; }
        else if (i < SEG2) { src = Wh; li = i - SEG1; dh = (uint2*)(g_wh + WOFF_Q); dl = (uint2*)(g_wl + WOFF_Q); }
        else if (i < SEG3) { src = Wk; li = i - SEG2; dh = (uint2*)(g_wh + WOFF_K); dl = (uint2*)(g_wl + WOFF_K); }
        else               { src = Wv; li = i - SEG3; dh = (uint2*)(g_wh + WOFF_V); dl = (uint2*)(g_wl + WOFF_V); }
        uint2 hh, ll; split4(src[li], hh, ll);
        dh[li] = hh; dl[li] = ll;
    }
}

// =====================================================================
// MEGA kernel: 1024 CTAs, role by parity (R13 winner, unchanged).
// =====================================================================
#define AE 5120
#define BE 2304
#define STG (2 * AE + 2 * BE)
#define MEGA_SMEM (2 * STG * 2)
#define CTX_SMEM (2 * STG * 2)

__global__ __launch_bounds__(256) void mega_tc(
    const int* __restrict__ xb, float* __restrict__ attn)
{
    extern __shared__ __align__(16) __nv_bfloat16 dsm[];
    const int bidx = blockIdx.x;

    if (bidx & 1) {
        const int z = bidx >> 1;
        const int rbase = z * 16;
        const int m0 = rbase & ~127;
        const int zs4 = (g_foff[xb[m0]] & ~63) >> 2;
        const int ze4 = (min(NF, (g_foff[xb[m0 + 127] + 1] + 63) & ~63)) >> 2;
        const float4 zv = make_float4(0.f, 0.f, 0.f, 0.f);
        const int t = threadIdx.x;
#pragma unroll 1
        for (int rr = 0; rr < 16; rr++) {
            float4* p = (float4*)(attn + (size_t)(rbase + rr) * NF);
            for (int i = t; i < zs4; i += 256) p[i] = zv;
            for (int i = ze4 + t; i < (NF >> 2); i += 256) p[i] = zv;
        }
        return;
    }

    const int b = bidx >> 1;
    const int tid = threadIdx.x, lane = tid & 31, wid = tid >> 5, wm = wid >> 1, wn = wid & 1;

    const __nv_bfloat16 *Agh, *Agl, *Bgh, *Bgl;
    __nv_bfloat16 *Coh, *Col;
    int lda, ldb, ldc, K, m0, n0;
    if (b < 128) {
        Agh = g_hh; Agl = g_hl; lda = OUT_SIZE; K = OUT_SIZE;
        Bgh = g_wh + WOFF_Q; Bgl = g_wl + WOFF_Q; ldb = D_ATT; ldc = D_ATT;
        Coh = g_qh; Col = g_ql; m0 = (b >> 1) * 128; n0 = (b & 1) * 64;
    } else if (b < 256) {
        int lb = b - 128;
        Agh = g_fh; Agl = g_fl; lda = F_SIZE; K = F_SIZE;
        Bgh = g_wh + WOFF_K; Bgl = g_wl + WOFF_K; ldb = D_ATT; ldc = D_ATT;
        Coh = g_kh; Col = g_kl; m0 = (lb >> 1) * 128; n0 = (lb & 1) * 64;
    } else {
        int lb = b - 256;
        Agh = g_fh; Agl = g_fl; lda = F_SIZE; K = F_SIZE;
        Bgh = g_wh + WOFF_V; Bgl = g_wl + WOFF_V; ldb = OUT_SIZE; ldc = OUT_SIZE;
        Coh = g_vh; Col = g_vl; m0 = (lb >> 2) * 128; n0 = (lb & 3) * 64;
    }

    auto pf = [&](int k0, int s) {
        __nv_bfloat16* bs = dsm + s * STG;
#pragma unroll
        for (int i = 0; i < 2; i++) {
            int idx = tid + i * 256, r = idx >> 2, c8 = (idx & 3) * 8;
            cpa16(bs + r * 40 + c8, Agh + (size_t)(m0 + r) * lda + k0 + c8);
            cpa16(bs + AE + r * 40 + c8, Agl + (size_t)(m0 + r) * lda + k0 + c8);
        }
        {
            int r = tid >> 3, c8 = (tid & 7) * 8;
            cpa16(bs + 2 * AE + r * 72 + c8, Bgh + (size_t)(k0 + r) * ldb + n0 + c8);
            cpa16(bs + 2 * AE + BE + r * 72 + c8, Bgl + (size_t)(k0 + r) * ldb + n0 + c8);
        }
        CPA_COMMIT;
    };

    float acc[2][4][4] = {};
    const unsigned smB = su(dsm);

    auto compute = [&](int s) {
        unsigned aB = smB + 2 * (s * STG);
        unsigned alB = aB + 2 * AE;
        unsigned bB = aB + 2 * (2 * AE);
        unsigned blB = bB + 2 * BE;
#pragma unroll
        for (int ks = 0; ks < 32; ks += 16) {
            unsigned ah[2][4], al[2][4], bh[2][4], bl[2][4];
#pragma unroll
            for (int mf = 0; mf < 2; mf++) {
                unsigned off = 2u * ((wm * 32 + mf * 16 + (lane & 15)) * 40 + ks + ((lane >> 4) << 3));
                ldsm4(ah[mf], aB + off);
                ldsm4(al[mf], alB + off);
            }
#pragma unroll
            for (int p = 0; p < 2; p++) {
                unsigned off = 2u * ((ks + (lane & 15)) * 72 + wn * 32 + p * 16 + ((lane >> 4) << 3));
                ldsm4t(bh[p], bB + off);
                ldsm4t(bl[p], blB + off);
            }
#pragma unroll
            for (int mf = 0; mf < 2; mf++)
#pragma unroll
                for (int nf = 0; nf < 4; nf++) {
                    unsigned b0 = bh[nf >> 1][(nf & 1) * 2], b1 = bh[nf >> 1][(nf & 1) * 2 + 1];
                    unsigned c0 = bl[nf >> 1][(nf & 1) * 2], c1 = bl[nf >> 1][(nf & 1) * 2 + 1];
                    mma_bf(acc[mf][nf], ah[mf], b0, b1);
                    mma_bf(acc[mf][nf], al[mf], b0, b1);
                    mma_bf(acc[mf][nf], ah[mf], c0, c1);
                }
        }
    };

    const int nst = K / 32;
    pf(0, 0);
    for (int t = 0; t < nst; t++) {
        int s = t & 1;
        if (t + 1 < nst) { pf((t + 1) * 32, s ^ 1); CPA_WAIT1; } else { CPA_WAIT0; }
        __syncthreads();
        compute(s);
        __syncthreads();
    }

#pragma unroll
    for (int mf = 0; mf < 2; mf++)
#pragma unroll
        for (int nf = 0; nf < 4; nf++) {
            int row = m0 + wm * 32 + mf * 16 + (lane >> 2);
            int col = n0 + wn * 32 + nf * 8 + ((lane & 3) << 1);
            unsigned h0, l0, h1, l1;
            split2w(acc[mf][nf][0], acc[mf][nf][1], h0, l0);
            split2w(acc[mf][nf][2], acc[mf][nf][3], h1, l1);
            *(unsigned*)(Coh + (size_t)row * ldc + col) = h0;
            *(unsigned*)(Col + (size_t)row * ldc + col) = l0;
            *(unsigned*)(Coh + (size_t)(row + 8) * ldc + col) = h1;
            *(unsigned*)(Col + (size_t)(row + 8) * ldc + col) = l1;
        }
}

// =====================================================================
// scores: BM=64 rowblocks, double-buffered K tiles (same 104448 B smem).
// 8 warps as 2m x 4n; warp tile 32x16. grid (8, NX/64).
// =====================================================================
#define QLD 136
#define QE2 (64 * QLD)
#define KE (64 * QLD)
#define SC_SMEM ((2 * QE2 + 4 * KE) * 2)   // 104448 B

__global__ __launch_bounds__(256) void scores_tc(
    const int* __restrict__ xb, float* __restrict__ attn)
{
    extern __shared__ __align__(16) __nv_bfloat16 dsm[];
    __nv_bfloat16* Qh = dsm;
    __nv_bfloat16* Ql = Qh + QE2;
    __nv_bfloat16* Kb = Ql + QE2;   // 2 buffers of [Kh(KE), Kl(KE)]

    const int tid = threadIdx.x, lane = tid & 31, wid = tid >> 5;
    const int wm = wid >> 2, wn = wid & 3;
    const int m0 = blockIdx.y * 64;
    const int colpart = blockIdx.x;

    const int jmin = g_foff[xb[m0]];
    const int jmax = g_foff[xb[m0 + 63] + 1];
    const int jt_lo = jmin >> 6, jt_hi = (jmax + 63) >> 6;
    int jt = jt_lo + colpart;
    if (jt >= jt_hi) return;

    int fs[2][2], fe[2][2];
#pragma unroll
    for (int mf = 0; mf < 2; mf++)
#pragma unroll
        for (int hh = 0; hh < 2; hh++) {
            int row = m0 + wm * 32 + mf * 16 + (lane >> 2) + hh * 8;
            int g = xb[row];
            fs[mf][hh] = g_foff[g]; fe[mf][hh] = g_foff[g + 1];
        }

    // Q tile (64 rows), group 0
#pragma unroll
    for (int i = 0; i < 4; i++) {
        int idx = tid + i * 256, r = idx >> 4, c8 = (idx & 15) * 8;
        cpa16(Qh + r * QLD + c8, g_qh + (size_t)(m0 + r) * D_ATT + c8);
        cpa16(Ql + r * QLD + c8, g_ql + (size_t)(m0 + r) * D_ATT + c8);
    }
    CPA_COMMIT;

    auto loadK = [&](int j0, int s) {
        __nv_bfloat16* kh = Kb + s * (2 * KE);
        __nv_bfloat16* kl = kh + KE;
#pragma unroll
        for (int i = 0; i < 4; i++) {
            int idx = tid + i * 256, r = idx >> 4, c8 = (idx & 15) * 8;
            cpa16(kh + r * QLD + c8, g_kh + (size_t)(j0 + r) * D_ATT + c8);
            cpa16(kl + r * QLD + c8, g_kl + (size_t)(j0 + r) * D_ATT + c8);
        }
        CPA_COMMIT;
    };

    const unsigned qhB = su(Qh), qlB = su(Ql), kbB = su(Kb);

    loadK(jt << 6, 0);
    int s = 0;
    for (; jt < jt_hi; jt += 8, s ^= 1) {
        if (jt + 8 < jt_hi) { loadK((jt + 8) << 6, s ^ 1); CPA_WAIT1; }
        else { CPA_WAIT0; }
        __syncthreads();

        const unsigned khB = kbB + 2u * (s * (2 * KE));
        const unsigned klB = khB + 2u * KE;

        float acc[2][2][4] = {};
#pragma unroll
        for (int d0 = 0; d0 < D_ATT; d0 += 16) {
            unsigned ah[2][4], al[2][4], bh[4], bl[4];
#pragma unroll
            for (int mf = 0; mf < 2; mf++) {
                unsigned off = 2u * ((wm * 32 + mf * 16 + (lane & 15)) * QLD + d0 + ((lane >> 4) << 3));
                ldsm4(ah[mf], qhB + off);
                ldsm4(al[mf], qlB + off);
            }
            {
                unsigned off = 2u * ((wn * 16 + ((lane >> 4) << 3) + (lane & 7)) * QLD + d0 + (lane & 8));
                ldsm4(bh, khB + off);
                ldsm4(bl, klB + off);
            }
#pragma unroll
            for (int mf = 0; mf < 2; mf++)
#pragma unroll
                for (int nf = 0; nf < 2; nf++) {
                    unsigned b0 = bh[nf * 2], b1 = bh[nf * 2 + 1];
                    unsigned c0 = bl[nf * 2], c1 = bl[nf * 2 + 1];
                    mma_bf(acc[mf][nf], ah[mf], b0, b1);
                    mma_bf(acc[mf][nf], al[mf], b0, b1);
                    mma_bf(acc[mf][nf], ah[mf], c0, c1);
                }
        }
        __syncthreads();

        const int j0 = jt << 6;
#pragma unroll
        for (int mf = 0; mf < 2; mf++) {
            int row = m0 + wm * 32 + mf * 16 + (lane >> 2);
#pragma unroll
            for (int nf = 0; nf < 2; nf++) {
                int col = j0 + wn * 16 + nf * 8 + ((lane & 3) << 1);
                float2 w0, w1;
                w0.x = (col >= fs[mf][0] && col < fe[mf][0])         ? acc[mf][nf][0] : 0.f;
                w0.y = (col + 1 >= fs[mf][0] && col + 1 < fe[mf][0]) ? acc[mf][nf][1] : 0.f;
                w1.x = (col >= fs[mf][1] && col < fe[mf][1])         ? acc[mf][nf][2] : 0.f;
                w1.y = (col + 1 >= fs[mf][1] && col + 1 < fe[mf][1]) ? acc[mf][nf][3] : 0.f;
                *(float2*)(attn + (size_t)row * NF + col) = w0;
                *(float2*)(attn + (size_t)(row + 8) * NF + col) = w1;
            }
        }
    }
}

// =====================================================================
// softmax: online single-pass (max,sum), then normalize (R5 version).
// =====================================================================
__global__ __launch_bounds__(128) void softmax_kernel(
    float* __restrict__ attn, const int* __restrict__ xb)
{
    const int i = blockIdx.x, t = threadIdx.x;
    const int g = xb[i], fs = g_foff[g], fe = g_foff[g + 1];
    float* row = attn + (size_t)i * NF;
    __shared__ float redm[4], reds[4];

    float m = -3.0e38f, s = 0.f;
    for (int j = fs + t; j < fe; j += 128) {
        float v = row[j];
        float mn = fmaxf(m, v);
        s = s * __expf(m - mn) + __expf(v - mn);
        m = mn;
    }
#pragma unroll
    for (int o = 16; o; o >>= 1) {
        float m2 = __shfl_xor_sync(0xffffffffu, m, o);
        float s2 = __shfl_xor_sync(0xffffffffu, s, o);
        float mn = fmaxf(m, m2);
        s = s * __expf(m - mn) + s2 * __expf(m2 - mn);
        m = mn;
    }
    if ((t & 31) == 0) { redm[t >> 5] = m; reds[t >> 5] = s; }
    __syncthreads();
    float mt = fmaxf(fmaxf(redm[0], redm[1]), fmaxf(redm[2], redm[3]));
    float st = reds[0] * __expf(redm[0] - mt) + reds[1] * __expf(redm[1] - mt)
             + reds[2] * __expf(redm[2] - mt) + reds[3] * __expf(redm[3] - mt);
    float inv = 1.f / st;

    for (int j = fs + t; j < fe; j += 128) row[j] = __expf(row[j] - mt) * inv;
}

// =====================================================================
// context: attn(band fp32) @ value(bf16 pre-split)
// =====================================================================
__global__ __launch_bounds__(256) void context_tc(
    const float* __restrict__ attn, float* __restrict__ ctx,
    const int* __restrict__ xb)
{
    extern __shared__ __align__(16) __nv_bfloat16 dsm[];
    const int tid = threadIdx.x, lane = tid & 31, wid = tid >> 5, wm = wid >> 1, wn = wid & 1;
    const int m0 = blockIdx.y * 128, n0 = blockIdx.x * 64;

    const int g0 = xb[m0], g1 = xb[m0 + 127];
    const int kbeg = g_foff[g0] & ~31;
    const int kend = g_foff[g1 + 1];
    const int nst = (kend - kbeg + 31) >> 5;

    float4 areg[4];
    auto ldgA = [&](int k0) {
#pragma unroll
        for (int i = 0; i < 4; i++) {
            int idx = tid + i * 256, r = idx >> 3, c4 = (idx & 7) << 2;
            areg[i] = *(const float4*)(attn + (size_t)(m0 + r) * NF + k0 + c4);
        }
    };
    auto stsA = [&](int s) {
        __nv_bfloat16* bs = dsm + s * STG;
#pragma unroll
        for (int i = 0; i < 4; i++) {
            int idx = tid + i * 256, r = idx >> 3, c4 = (idx & 7) << 2;
            uint2 h, l; split4(areg[i], h, l);
            *(uint2*)(bs + r * 40 + c4) = h;
            *(uint2*)(bs + AE + r * 40 + c4) = l;
        }
    };
    auto cpaB = [&](int k0, int s) {
        __nv_bfloat16* bs = dsm + s * STG + 2 * AE;
        int r = tid >> 3, c8 = (tid & 7) * 8;
        cpa16(bs + r * 72 + c8, g_vh + (size_t)(k0 + r) * OUT_SIZE + n0 + c8);
        cpa16(bs + BE + r * 72 + c8, g_vl + (size_t)(k0 + r) * OUT_SIZE + n0 + c8);
        CPA_COMMIT;
    };

    float acc[2][4][4] = {};
    const unsigned smB = su(dsm);

    auto compute = [&](int s) {
        unsigned aB = smB + 2 * (s * STG);
        unsigned alB = aB + 2 * AE;
        unsigned bB = aB + 2 * (2 * AE);
        unsigned blB = bB + 2 * BE;
#pragma unroll
        for (int ks = 0; ks < 32; ks += 16) {
            unsigned ah[2][4], al[2][4], bh[2][4], bl[2][4];
#pragma unroll
            for (int mf = 0; mf < 2; mf++) {
                unsigned off = 2u * ((wm * 32 + mf * 16 + (lane & 15)) * 40 + ks + ((lane >> 4) << 3));
                ldsm4(ah[mf], aB + off);
                ldsm4(al[mf], alB + off);
            }
#pragma unroll
            for (int p = 0; p < 2; p++) {
                unsigned off = 2u * ((ks + (lane & 15)) * 72 + wn * 32 + p * 16 + ((lane >> 4) << 3));
                ldsm4t(bh[p], bB + off);
                ldsm4t(bl[p], blB + off);
            }
#pragma unroll
            for (int mf = 0; mf < 2; mf++)
#pragma unroll
                for (int nf = 0; nf < 4; nf++) {
                    unsigned b0 = bh[nf >> 1][(nf & 1) * 2], b1 = bh[nf >> 1][(nf & 1) * 2 + 1];
                    unsigned c0 = bl[nf >> 1][(nf & 1) * 2], c1 = bl[nf >> 1][(nf & 1) * 2 + 1];
                    mma_bf(acc[mf][nf], ah[mf], b0, b1);
                    mma_bf(acc[mf][nf], al[mf], b0, b1);
                    mma_bf(acc[mf][nf], ah[mf], c0, c1);
                }
        }
    };

    ldgA(kbeg);
    stsA(0);
    cpaB(kbeg, 0);
    for (int t = 0; t < nst; t++) {
        int s = t & 1;
        bool more = (t + 1 < nst);
        if (more) { ldgA(kbeg + (t + 1) * 32); cpaB(kbeg + (t + 1) * 32, s ^ 1); CPA_WAIT1; }
        else { CPA_WAIT0; }
        __syncthreads();
        compute(s);
        __syncthreads();
        if (more) stsA(s ^ 1);
    }

#pragma unroll
    for (int mf = 0; mf < 2; mf++)
#pragma unroll
        for (int nf = 0; nf < 4; nf++) {
            int row = m0 + wm * 32 + mf * 16 + (lane >> 2);
            int col = n0 + wn * 32 + nf * 8 + ((lane & 3) << 1);
            *(float2*)(ctx + (size_t)row * OUT_SIZE + col) = make_float2(acc[mf][nf][0], acc[mf][nf][1]);
            *(float2*)(ctx + (size_t)(row + 8) * OUT_SIZE + col) = make_float2(acc[mf][nf][2], acc[mf][nf][3]);
        }
}

// ---------------- launch (single stream) ----------------
extern "C" void kernel_launch(void* const* d_in, const int* in_sizes, int n_in,
                              void* d_out, int out_size)
{
    const float* f       = (const float*)d_in[0];
    const float* h       = (const float*)d_in[2];
    const int*   f_batch = (const int*)  d_in[5];
    const int*   x_batch = (const int*)  d_in[6];
    const float* W_h     = (const float*)d_in[8];
    const float* W_key   = (const float*)d_in[9];
    const float* W_value = (const float*)d_in[10];

    float* out  = (float*)d_out;
    float* ctx  = out;
    float* attn = out + (size_t)NX * OUT_SIZE;

    cudaFuncSetAttribute(mega_tc,    cudaFuncAttributeMaxDynamicSharedMemorySize, MEGA_SMEM);
    cudaFuncSetAttribute(scores_tc,  cudaFuncAttributeMaxDynamicSharedMemorySize, SC_SMEM);
    cudaFuncSetAttribute(context_tc, cudaFuncAttributeMaxDynamicSharedMemorySize, CTX_SMEM);

    offsets_kernel<<<1, 32>>>(f_batch);
    split_all<<<1024, 256>>>((const float4*)f, (const float4*)h,
                             (const float4*)W_h, (const float4*)W_key, (const float4*)W_value);
    mega_tc<<<1024, 256, MEGA_SMEM>>>(x_batch, attn);
    scores_tc<<<dim3(8, NX / 64), 256, SC_SMEM>>>(x_batch, attn);
    softmax_kernel<<<NX, 128>>>(attn, x_batch);
    context_tc<<<dim3(OUT_SIZE / 64, NX / 128), 256, CTX_SMEM>>>(attn, ctx, x_batch);
}

// round 15
// speedup vs baseline: 1.0405x; 1.0405x over previous
#include <cuda_runtime.h>
#include <cuda_bf16.h>
#include <cstdint>

#define NX 8192
#define NF 8192
#define F_SIZE 512
#define OUT_SIZE 256
#define D_ATT 128
#define N_GRAPHS 16

// ---------------- scratch ----------------
__device__ int g_foff[N_GRAPHS + 1];
__device__ __nv_bfloat16 g_qh[NX * D_ATT],   g_ql[NX * D_ATT];
__device__ __nv_bfloat16 g_kh[NF * D_ATT],   g_kl[NF * D_ATT];
__device__ __nv_bfloat16 g_vh[NF * OUT_SIZE], g_vl[NF * OUT_SIZE];

__global__ void offsets_kernel(const int* __restrict__ f_batch) {
    int g = threadIdx.x;
    if (g > N_GRAPHS) return;
    int lo = 0, hi = NF;
    while (lo < hi) { int mid = (lo + hi) >> 1; if (f_batch[mid] < g) lo = mid + 1; else hi = mid; }
    g_foff[g] = lo;
}

// ---------------- helpers ----------------
__device__ __forceinline__ unsigned su(const void* p) { return (unsigned)__cvta_generic_to_shared(p); }
__device__ __forceinline__ void cpa16(void* dst, const void* src) {
    asm volatile("cp.async.cg.shared.global [%0],[%1],16;\n" :: "r"(su(dst)), "l"(src));
}
#define CPA_COMMIT asm volatile("cp.async.commit_group;\n")
#define CPA_WAIT1  asm volatile("cp.async.wait_group 1;\n")
#define CPA_WAIT0  asm volatile("cp.async.wait_group 0;\n")

__device__ __forceinline__ void ldsm4(unsigned r[4], unsigned a) {
    asm volatile("ldmatrix.sync.aligned.m8n8.x4.shared.b16 {%0,%1,%2,%3},[%4];"
        : "=r"(r[0]), "=r"(r[1]), "=r"(r[2]), "=r"(r[3]) : "r"(a));
}
__device__ __forceinline__ void ldsm4t(unsigned r[4], unsigned a) {
    asm volatile("ldmatrix.sync.aligned.m8n8.x4.trans.shared.b16 {%0,%1,%2,%3},[%4];"
        : "=r"(r[0]), "=r"(r[1]), "=r"(r[2]), "=r"(r[3]) : "r"(a));
}
__device__ __forceinline__ void mma_bf(float d[4], const unsigned a[4], unsigned b0, unsigned b1) {
    asm volatile("mma.sync.aligned.m16n8k16.row.col.f32.bf16.bf16.f32 "
        "{%0,%1,%2,%3},{%4,%5,%6,%7},{%8,%9},{%0,%1,%2,%3};"
        : "+f"(d[0]), "+f"(d[1]), "+f"(d[2]), "+f"(d[3])
        : "r"(a[0]), "r"(a[1]), "r"(a[2]), "r"(a[3]), "r"(b0), "r"(b1));
}
__device__ __forceinline__ unsigned pk2(__nv_bfloat16 a, __nv_bfloat16 b) {
    __nv_bfloat162 t(a, b); return *reinterpret_cast<unsigned*>(&t);
}
__device__ __forceinline__ void split4(float4 v, uint2& hi, uint2& lo) {
    __nv_bfloat16 h0 = __float2bfloat16_rn(v.x), h1 = __float2bfloat16_rn(v.y);
    __nv_bfloat16 h2 = __float2bfloat16_rn(v.z), h3 = __float2bfloat16_rn(v.w);
    __nv_bfloat16 l0 = __float2bfloat16_rn(v.x - __bfloat162float(h0));
    __nv_bfloat16 l1 = __float2bfloat16_rn(v.y - __bfloat162float(h1));
    __nv_bfloat16 l2 = __float2bfloat16_rn(v.z - __bfloat162float(h2));
    __nv_bfloat16 l3 = __float2bfloat16_rn(v.w - __bfloat162float(h3));
    hi.x = pk2(h0, h1); hi.y = pk2(h2, h3);
    lo.x = pk2(l0, l1); lo.y = pk2(l2, l3);
}
__device__ __forceinline__ void split2w(float x, float y, unsigned& h, unsigned& l) {
    __nv_bfloat16 hx = __float2bfloat16_rn(x), hy = __float2bfloat16_rn(y);
    h = pk2(hx, hy);
    l = pk2(__float2bfloat16_rn(x - __bfloat162float(hx)),
            __float2bfloat16_rn(y - __bfloat162float(hy)));
}

// =====================================================================
// MEGA kernel: 1024 CTAs, role by parity.
//   odd  CTA: zero 16 rows' band complement of attn.
//   even CTA: one 128x64 projection tile reading fp32 inputs directly
//             (LDG -> register split -> STS bf16 hi/lo), double buffered.
// =====================================================================
#define AE 5120
#define BE 2304
#define STG (2 * AE + 2 * BE)
#define MEGA_SMEM (2 * STG * 2)
#define CTX_SMEM (2 * STG * 2)

__global__ __launch_bounds__(256) void mega_tc(
    const int* __restrict__ xb, float* __restrict__ attn,
    const float* __restrict__ fI, const float* __restrict__ hI,
    const float* __restrict__ Wh, const float* __restrict__ Wk,
    const float* __restrict__ Wv)
{
    extern __shared__ __align__(16) __nv_bfloat16 dsm[];
    const int bidx = blockIdx.x;

    if (bidx & 1) {
        const int z = bidx >> 1;
        const int rbase = z * 16;
        const int m0 = rbase & ~127;
        const int zs4 = (g_foff[xb[m0]] & ~63) >> 2;
        const int ze4 = (min(NF, (g_foff[xb[m0 + 127] + 1] + 63) & ~63)) >> 2;
        const float4 zv = make_float4(0.f, 0.f, 0.f, 0.f);
        const int t = threadIdx.x;
#pragma unroll 1
        for (int rr = 0; rr < 16; rr++) {
            float4* p = (float4*)(attn + (size_t)(rbase + rr) * NF);
            for (int i = t; i < zs4; i += 256) p[i] = zv;
            for (int i = ze4 + t; i < (NF >> 2); i += 256) p[i] = zv;
        }
        return;
    }

    const int b = bidx >> 1;
    const int tid = threadIdx.x, lane = tid & 31, wid = tid >> 5, wm = wid >> 1, wn = wid & 1;

    const float *Ag, *Bg;
    __nv_bfloat16 *Coh, *Col;
    int lda, ldb, ldc, K, m0, n0;
    if (b < 128) {
        Ag = hI; lda = OUT_SIZE; K = OUT_SIZE;
        Bg = Wh; ldb = D_ATT; ldc = D_ATT;
        Coh = g_qh; Col = g_ql; m0 = (b >> 1) * 128; n0 = (b & 1) * 64;
    } else if (b < 256) {
        int lb = b - 128;
        Ag = fI; lda = F_SIZE; K = F_SIZE;
        Bg = Wk; ldb = D_ATT; ldc = D_ATT;
        Coh = g_kh; Col = g_kl; m0 = (lb >> 1) * 128; n0 = (lb & 1) * 64;
    } else {
        int lb = b - 256;
        Ag = fI; lda = F_SIZE; K = F_SIZE;
        Bg = Wv; ldb = OUT_SIZE; ldc = OUT_SIZE;
        Coh = g_vh; Col = g_vl; m0 = (lb >> 2) * 128; n0 = (lb & 3) * 64;
    }

    float4 areg[4], breg[2];
    auto ldgAB = [&](int k0) {
#pragma unroll
        for (int i = 0; i < 4; i++) {
            int idx = tid + i * 256, r = idx >> 3, c4 = (idx & 7) << 2;
            areg[i] = *(const float4*)(Ag + (size_t)(m0 + r) * lda + k0 + c4);
        }
#pragma unroll
        for (int i = 0; i < 2; i++) {
            int idx = tid + i * 256, r = idx >> 4, c4 = (idx & 15) << 2;
            breg[i] = *(const float4*)(Bg + (size_t)(k0 + r) * ldb + n0 + c4);
        }
    };
    auto stsAB = [&](int s) {
        __nv_bfloat16* bs = dsm + s * STG;
#pragma unroll
        for (int i = 0; i < 4; i++) {
            int idx = tid + i * 256, r = idx >> 3, c4 = (idx & 7) << 2;
            uint2 h_, l_; split4(areg[i], h_, l_);
            *(uint2*)(bs + r * 40 + c4) = h_;
            *(uint2*)(bs + AE + r * 40 + c4) = l_;
        }
#pragma unroll
        for (int i = 0; i < 2; i++) {
            int idx = tid + i * 256, r = idx >> 4, c4 = (idx & 15) << 2;
            uint2 h_, l_; split4(breg[i], h_, l_);
            *(uint2*)(bs + 2 * AE + r * 72 + c4) = h_;
            *(uint2*)(bs + 2 * AE + BE + r * 72 + c4) = l_;
        }
    };

    float acc[2][4][4] = {};
    const unsigned smB = su(dsm);

    auto compute = [&](int s) {
        unsigned aB = smB + 2 * (s * STG);
        unsigned alB = aB + 2 * AE;
        unsigned bB = aB + 2 * (2 * AE);
        unsigned blB = bB + 2 * BE;
#pragma unroll
        for (int ks = 0; ks < 32; ks += 16) {
            unsigned ah[2][4], al[2][4], bh[2][4], bl[2][4];
#pragma unroll
            for (int mf = 0; mf < 2; mf++) {
                unsigned off = 2u * ((wm * 32 + mf * 16 + (lane & 15)) * 40 + ks + ((lane >> 4) << 3));
                ldsm4(ah[mf], aB + off);
                ldsm4(al[mf], alB + off);
            }
#pragma unroll
            for (int p = 0; p < 2; p++) {
                unsigned off = 2u * ((ks + (lane & 15)) * 72 + wn * 32 + p * 16 + ((lane >> 4) << 3));
                ldsm4t(bh[p], bB + off);
                ldsm4t(bl[p], blB + off);
            }
#pragma unroll
            for (int mf = 0; mf < 2; mf++)
#pragma unroll
                for (int nf = 0; nf < 4; nf++) {
                    unsigned b0 = bh[nf >> 1][(nf & 1) * 2], b1 = bh[nf >> 1][(nf & 1) * 2 + 1];
                    unsigned c0 = bl[nf >> 1][(nf & 1) * 2], c1 = bl[nf >> 1][(nf & 1) * 2 + 1];
                    mma_bf(acc[mf][nf], ah[mf], b0, b1);
                    mma_bf(acc[mf][nf], al[mf], b0, b1);
                    mma_bf(acc[mf][nf], ah[mf], c0, c1);
                }
        }
    };

    const int nst = K / 32;
    ldgAB(0);
    stsAB(0);
    for (int t = 0; t < nst; t++) {
        int s = t & 1;
        bool more = (t + 1 < nst);
        if (more) ldgAB((t + 1) * 32);
        __syncthreads();
        compute(s);
        __syncthreads();
        if (more) stsAB(s ^ 1);
    }

#pragma unroll
    for (int mf = 0; mf < 2; mf++)
#pragma unroll
        for (int nf = 0; nf < 4; nf++) {
            int row = m0 + wm * 32 + mf * 16 + (lane >> 2);
            int col = n0 + wn * 32 + nf * 8 + ((lane & 3) << 1);
            unsigned h0, l0, h1, l1;
            split2w(acc[mf][nf][0], acc[mf][nf][1], h0, l0);
            split2w(acc[mf][nf][2], acc[mf][nf][3], h1, l1);
            *(unsigned*)(Coh + (size_t)row * ldc + col) = h0;
            *(unsigned*)(Col + (size_t)row * ldc + col) = l0;
            *(unsigned*)(Coh + (size_t)(row + 8) * ldc + col) = h1;
            *(unsigned*)(Col + (size_t)(row + 8) * ldc + col) = l1;
        }
}

// =====================================================================
// scores: R13 winner (BM=128, 2 CTA/SM, single K buffer).
// =====================================================================
#define QLD 136
#define QE (128 * QLD)
#define KE (64 * QLD)
#define SC_SMEM ((2 * QE + 2 * KE) * 2)

__global__ __launch_bounds__(256) void scores_tc(
    const int* __restrict__ xb, float* __restrict__ attn)
{
    extern __shared__ __align__(16) __nv_bfloat16 dsm[];
    __nv_bfloat16* Qh = dsm;
    __nv_bfloat16* Ql = Qh + QE;
    __nv_bfloat16* Kh = Ql + QE;
    __nv_bfloat16* Kl = Kh + KE;

    const int tid = threadIdx.x, lane = tid & 31, wid = tid >> 5, wm = wid >> 1, wn = wid & 1;
    const int m0 = blockIdx.y * 128;

    const int jmin = g_foff[xb[m0]];
    const int jmax = g_foff[xb[m0 + 127] + 1];
    const int jt_lo = jmin >> 6, jt_hi = (jmax + 63) >> 6;
    if (jt_lo + (int)blockIdx.x >= jt_hi) return;

    int fs[2][2], fe[2][2];
#pragma unroll
    for (int mf = 0; mf < 2; mf++)
#pragma unroll
        for (int hh = 0; hh < 2; hh++) {
            int row = m0 + wm * 32 + mf * 16 + (lane >> 2) + hh * 8;
            int g = xb[row];
            fs[mf][hh] = g_foff[g]; fe[mf][hh] = g_foff[g + 1];
        }

#pragma unroll
    for (int i = 0; i < 8; i++) {
        int idx = tid + i * 256, r = idx >> 4, c8 = (idx & 15) * 8;
        cpa16(Qh + r * QLD + c8, g_qh + (size_t)(m0 + r) * D_ATT + c8);
        cpa16(Ql + r * QLD + c8, g_ql + (size_t)(m0 + r) * D_ATT + c8);
    }
    CPA_COMMIT;

    const unsigned qhB = su(Qh), qlB = su(Ql), khB = su(Kh), klB = su(Kl);

    for (int jt = jt_lo + blockIdx.x; jt < jt_hi; jt += 8) {
        const int j0 = jt << 6;
#pragma unroll
        for (int i = 0; i < 4; i++) {
            int idx = tid + i * 256, r = idx >> 4, c8 = (idx & 15) * 8;
            cpa16(Kh + r * QLD + c8, g_kh + (size_t)(j0 + r) * D_ATT + c8);
            cpa16(Kl + r * QLD + c8, g_kl + (size_t)(j0 + r) * D_ATT + c8);
        }
        CPA_COMMIT;
        CPA_WAIT0;
        __syncthreads();

        float acc[2][4][4] = {};
#pragma unroll
        for (int d0 = 0; d0 < D_ATT; d0 += 16) {
            unsigned ah[2][4], al[2][4], bh[2][4], bl[2][4];
#pragma unroll
            for (int mf = 0; mf < 2; mf++) {
                unsigned off = 2u * ((wm * 32 + mf * 16 + (lane & 15)) * QLD + d0 + ((lane >> 4) << 3));
                ldsm4(ah[mf], qhB + off);
                ldsm4(al[mf], qlB + off);
            }
#pragma unroll
            for (int p = 0; p < 2; p++) {
                unsigned off = 2u * ((wn * 32 + p * 16 + ((lane >> 4) << 3) + (lane & 7)) * QLD + d0 + (lane & 8));
                ldsm4(bh[p], khB + off);
                ldsm4(bl[p], klB + off);
            }
#pragma unroll
            for (int mf = 0; mf < 2; mf++)
#pragma unroll
                for (int nf = 0; nf < 4; nf++) {
                    unsigned b0 = bh[nf >> 1][(nf & 1) * 2], b1 = bh[nf >> 1][(nf & 1) * 2 + 1];
                    unsigned c0 = bl[nf >> 1][(nf & 1) * 2], c1 = bl[nf >> 1][(nf & 1) * 2 + 1];
                    mma_bf(acc[mf][nf], ah[mf], b0, b1);
                    mma_bf(acc[mf][nf], al[mf], b0, b1);
                    mma_bf(acc[mf][nf], ah[mf], c0, c1);
                }
        }
        __syncthreads();

#pragma unroll
        for (int mf = 0; mf < 2; mf++) {
            int row = m0 + wm * 32 + mf * 16 + (lane >> 2);
#pragma unroll
            for (int nf = 0; nf < 4; nf++) {
                int col = j0 + wn * 32 + nf * 8 + ((lane & 3) << 1);
                float2 w0, w1;
                w0.x = (col >= fs[mf][0] && col < fe[mf][0])         ? acc[mf][nf][0] : 0.f;
                w0.y = (col + 1 >= fs[mf][0] && col + 1 < fe[mf][0]) ? acc[mf][nf][1] : 0.f;
                w1.x = (col >= fs[mf][1] && col < fe[mf][1])         ? acc[mf][nf][2] : 0.f;
                w1.y = (col + 1 >= fs[mf][1] && col + 1 < fe[mf][1]) ? acc[mf][nf][3] : 0.f;
                *(float2*)(attn + (size_t)row * NF + col) = w0;
                *(float2*)(attn + (size_t)(row + 8) * NF + col) = w1;
            }
        }
    }
}

// =====================================================================
// softmax: online single-pass (max,sum), then normalize.
// =====================================================================
__global__ __launch_bounds__(128) void softmax_kernel(
    float* __restrict__ attn, const int* __restrict__ xb)
{
    const int i = blockIdx.x, t = threadIdx.x;
    const int g = xb[i], fs = g_foff[g], fe = g_foff[g + 1];
    float* row = attn + (size_t)i * NF;
    __shared__ float redm[4], reds[4];

    float m = -3.0e38f, s = 0.f;
    for (int j = fs + t; j < fe; j += 128) {
        float v = row[j];
        float mn = fmaxf(m, v);
        s = s * __expf(m - mn) + __expf(v - mn);
        m = mn;
    }
#pragma unroll
    for (int o = 16; o; o >>= 1) {
        float m2 = __shfl_xor_sync(0xffffffffu, m, o);
        float s2 = __shfl_xor_sync(0xffffffffu, s, o);
        float mn = fmaxf(m, m2);
        s = s * __expf(m - mn) + s2 * __expf(m2 - mn);
        m = mn;
    }
    if ((t & 31) == 0) { redm[t >> 5] = m; reds[t >> 5] = s; }
    __syncthreads();
    float mt = fmaxf(fmaxf(redm[0], redm[1]), fmaxf(redm[2], redm[3]));
    float st = reds[0] * __expf(redm[0] - mt) + reds[1] * __expf(redm[1] - mt)
             + reds[2] * __expf(redm[2] - mt) + reds[3] * __expf(redm[3] - mt);
    float inv = 1.f / st;

    for (int j = fs + t; j < fe; j += 128) row[j] = __expf(row[j] - mt) * inv;
}

// =====================================================================
// context: attn(band fp32) @ value(bf16 pre-split)
// =====================================================================
__global__ __launch_bounds__(256) void context_tc(
    const float* __restrict__ attn, float* __restrict__ ctx,
    const int* __restrict__ xb)
{
    extern __shared__ __align__(16) __nv_bfloat16 dsm[];
    const int tid = threadIdx.x, lane = tid & 31, wid = tid >> 5, wm = wid >> 1, wn = wid & 1;
    const int m0 = blockIdx.y * 128, n0 = blockIdx.x * 64;

    const int g0 = xb[m0], g1 = xb[m0 + 127];
    const int kbeg = g_foff[g0] & ~31;
    const int kend = g_foff[g1 + 1];
    const int nst = (kend - kbeg + 31) >> 5;

    float4 areg[4];
    auto ldgA = [&](int k0) {
#pragma unroll
        for (int i = 0; i < 4; i++) {
            int idx = tid + i * 256, r = idx >> 3, c4 = (idx & 7) << 2;
            areg[i] = *(const float4*)(attn + (size_t)(m0 + r) * NF + k0 + c4);
        }
    };
    auto stsA = [&](int s) {
        __nv_bfloat16* bs = dsm + s * STG;
#pragma unroll
        for (int i = 0; i < 4; i++) {
            int idx = tid + i * 256, r = idx >> 3, c4 = (idx & 7) << 2;
            uint2 h, l; split4(areg[i], h, l);
            *(uint2*)(bs + r * 40 + c4) = h;
            *(uint2*)(bs + AE + r * 40 + c4) = l;
        }
    };
    auto cpaB = [&](int k0, int s) {
        __nv_bfloat16* bs = dsm + s * STG + 2 * AE;
        int r = tid >> 3, c8 = (tid & 7) * 8;
        cpa16(bs + r * 72 + c8, g_vh + (size_t)(k0 + r) * OUT_SIZE + n0 + c8);
        cpa16(bs + BE + r * 72 + c8, g_vl + (size_t)(k0 + r) * OUT_SIZE + n0 + c8);
        CPA_COMMIT;
    };

    float acc[2][4][4] = {};
    const unsigned smB = su(dsm);

    auto compute = [&](int s) {
        unsigned aB = smB + 2 * (s * STG);
        unsigned alB = aB + 2 * AE;
        unsigned bB = aB + 2 * (2 * AE);
        unsigned blB = bB + 2 * BE;
#pragma unroll
        for (int ks = 0; ks < 32; ks += 16) {
            unsigned ah[2][4], al[2][4], bh[2][4], bl[2][4];
#pragma unroll
            for (int mf = 0; mf < 2; mf++) {
                unsigned off = 2u * ((wm * 32 + mf * 16 + (lane & 15)) * 40 + ks + ((lane >> 4) << 3));
                ldsm4(ah[mf], aB + off);
                ldsm4(al[mf], alB + off);
            }
#pragma unroll
            for (int p = 0; p < 2; p++) {
                unsigned off = 2u * ((ks + (lane & 15)) * 72 + wn * 32 + p * 16 + ((lane >> 4) << 3));
                ldsm4t(bh[p], bB + off);
                ldsm4t(bl[p], blB + off);
            }
#pragma unroll
            for (int mf = 0; mf < 2; mf++)
#pragma unroll
                for (int nf = 0; nf < 4; nf++) {
                    unsigned b0 = bh[nf >> 1][(nf & 1) * 2], b1 = bh[nf >> 1][(nf & 1) * 2 + 1];
                    unsigned c0 = bl[nf >> 1][(nf & 1) * 2], c1 = bl[nf >> 1][(nf & 1) * 2 + 1];
                    mma_bf(acc[mf][nf], ah[mf], b0, b1);
                    mma_bf(acc[mf][nf], al[mf], b0, b1);
                    mma_bf(acc[mf][nf], ah[mf], c0, c1);
                }
        }
    };

    ldgA(kbeg);
    stsA(0);
    cpaB(kbeg, 0);
    for (int t = 0; t < nst; t++) {
        int s = t & 1;
        bool more = (t + 1 < nst);
        if (more) { ldgA(kbeg + (t + 1) * 32); cpaB(kbeg + (t + 1) * 32, s ^ 1); CPA_WAIT1; }
        else { CPA_WAIT0; }
        __syncthreads();
        compute(s);
        __syncthreads();
        if (more) stsA(s ^ 1);
    }

#pragma unroll
    for (int mf = 0; mf < 2; mf++)
#pragma unroll
        for (int nf = 0; nf < 4; nf++) {
            int row = m0 + wm * 32 + mf * 16 + (lane >> 2);
            int col = n0 + wn * 32 + nf * 8 + ((lane & 3) << 1);
            *(float2*)(ctx + (size_t)row * OUT_SIZE + col) = make_float2(acc[mf][nf][0], acc[mf][nf][1]);
            *(float2*)(ctx + (size_t)(row + 8) * OUT_SIZE + col) = make_float2(acc[mf][nf][2], acc[mf][nf][3]);
        }
}

// ---------------- launch (single stream) ----------------
extern "C" void kernel_launch(void* const* d_in, const int* in_sizes, int n_in,
                              void* d_out, int out_size)
{
    const float* f       = (const float*)d_in[0];
    const float* h       = (const float*)d_in[2];
    const int*   f_batch = (const int*)  d_in[5];
    const int*   x_batch = (const int*)  d_in[6];
    const float* W_h     = (const float*)d_in[8];
    const float* W_key   = (const float*)d_in[9];
    const float* W_value = (const float*)d_in[10];

    float* out  = (float*)d_out;
    float* ctx  = out;
    float* attn = out + (size_t)NX * OUT_SIZE;

    cudaFuncSetAttribute(mega_tc,    cudaFuncAttributeMaxDynamicSharedMemorySize, MEGA_SMEM);
    cudaFuncSetAttribute(scores_tc,  cudaFuncAttributeMaxDynamicSharedMemorySize, SC_SMEM);
    cudaFuncSetAttribute(context_tc, cudaFuncAttributeMaxDynamicSharedMemorySize, CTX_SMEM);

    offsets_kernel<<<1, 32>>>(f_batch);
    // projections read fp32 inputs directly; zero role interleaved by parity
    mega_tc<<<1024, 256, MEGA_SMEM>>>(x_batch, attn, f, h, W_h, W_key, W_value);
    scores_tc<<<dim3(8, NX / 128), 256, SC_SMEM>>>(x_batch, attn);
    softmax_kernel<<<NX, 128>>>(attn, x_batch);
    context_tc<<<dim3(OUT_SIZE / 64, NX / 128), 256, CTX_SMEM>>>(attn, ctx, x_batch);
}

// round 16
// speedup vs baseline: 1.0532x; 1.0122x over previous
#include <cuda_runtime.h>
#include <cuda_bf16.h>
#include <cstdint>

#define NX 8192
#define NF 8192
#define F_SIZE 512
#define OUT_SIZE 256
#define D_ATT 128
#define N_GRAPHS 16

// ---------------- scratch ----------------
__device__ int g_foff[N_GRAPHS + 1];
__device__ __nv_bfloat16 g_qh[NX * D_ATT],   g_ql[NX * D_ATT];
__device__ __nv_bfloat16 g_kh[NF * D_ATT],   g_kl[NF * D_ATT];
__device__ __nv_bfloat16 g_vh[NF * OUT_SIZE], g_vl[NF * OUT_SIZE];

__global__ void offsets_kernel(const int* __restrict__ f_batch) {
    int g = threadIdx.x;
    if (g > N_GRAPHS) return;
    int lo = 0, hi = NF;
    while (lo < hi) { int mid = (lo + hi) >> 1; if (f_batch[mid] < g) lo = mid + 1; else hi = mid; }
    g_foff[g] = lo;
}

// ---------------- helpers ----------------
__device__ __forceinline__ unsigned su(const void* p) { return (unsigned)__cvta_generic_to_shared(p); }
__device__ __forceinline__ void cpa16(void* dst, const void* src) {
    asm volatile("cp.async.cg.shared.global [%0],[%1],16;\n" :: "r"(su(dst)), "l"(src));
}
#define CPA_COMMIT asm volatile("cp.async.commit_group;\n")
#define CPA_WAIT1  asm volatile("cp.async.wait_group 1;\n")
#define CPA_WAIT0  asm volatile("cp.async.wait_group 0;\n")

__device__ __forceinline__ void ldsm4(unsigned r[4], unsigned a) {
    asm volatile("ldmatrix.sync.aligned.m8n8.x4.shared.b16 {%0,%1,%2,%3},[%4];"
        : "=r"(r[0]), "=r"(r[1]), "=r"(r[2]), "=r"(r[3]) : "r"(a));
}
__device__ __forceinline__ void ldsm4t(unsigned r[4], unsigned a) {
    asm volatile("ldmatrix.sync.aligned.m8n8.x4.trans.shared.b16 {%0,%1,%2,%3},[%4];"
        : "=r"(r[0]), "=r"(r[1]), "=r"(r[2]), "=r"(r[3]) : "r"(a));
}
__device__ __forceinline__ void mma_bf(float d[4], const unsigned a[4], unsigned b0, unsigned b1) {
    asm volatile("mma.sync.aligned.m16n8k16.row.col.f32.bf16.bf16.f32 "
        "{%0,%1,%2,%3},{%4,%5,%6,%7},{%8,%9},{%0,%1,%2,%3};"
        : "+f"(d[0]), "+f"(d[1]), "+f"(d[2]), "+f"(d[3])
        : "r"(a[0]), "r"(a[1]), "r"(a[2]), "r"(a[3]), "r"(b0), "r"(b1));
}
__device__ __forceinline__ unsigned pk2(__nv_bfloat16 a, __nv_bfloat16 b) {
    __nv_bfloat162 t(a, b); return *reinterpret_cast<unsigned*>(&t);
}
__device__ __forceinline__ void split4(float4 v, uint2& hi, uint2& lo) {
    __nv_bfloat16 h0 = __float2bfloat16_rn(v.x), h1 = __float2bfloat16_rn(v.y);
    __nv_bfloat16 h2 = __float2bfloat16_rn(v.z), h3 = __float2bfloat16_rn(v.w);
    __nv_bfloat16 l0 = __float2bfloat16_rn(v.x - __bfloat162float(h0));
    __nv_bfloat16 l1 = __float2bfloat16_rn(v.y - __bfloat162float(h1));
    __nv_bfloat16 l2 = __float2bfloat16_rn(v.z - __bfloat162float(h2));
    __nv_bfloat16 l3 = __float2bfloat16_rn(v.w - __bfloat162float(h3));
    hi.x = pk2(h0, h1); hi.y = pk2(h2, h3);
    lo.x = pk2(l0, l1); lo.y = pk2(l2, l3);
}
__device__ __forceinline__ void split2w(float x, float y, unsigned& h, unsigned& l) {
    __nv_bfloat16 hx = __float2bfloat16_rn(x), hy = __float2bfloat16_rn(y);
    h = pk2(hx, hy);
    l = pk2(__float2bfloat16_rn(x - __bfloat162float(hx)),
            __float2bfloat16_rn(y - __bfloat162float(hy)));
}

// =====================================================================
// MEGA kernel (R15 winner, unchanged): parity roles, fp32 direct reads.
// =====================================================================
#define AE 5120
#define BE 2304
#define STG (2 * AE + 2 * BE)
#define MEGA_SMEM (2 * STG * 2)
#define CTX_SMEM (2 * STG * 2)

__global__ __launch_bounds__(256) void mega_tc(
    const int* __restrict__ xb, float* __restrict__ attn,
    const float* __restrict__ fI, const float* __restrict__ hI,
    const float* __restrict__ Wh, const float* __restrict__ Wk,
    const float* __restrict__ Wv)
{
    extern __shared__ __align__(16) __nv_bfloat16 dsm[];
    const int bidx = blockIdx.x;

    if (bidx & 1) {
        const int z = bidx >> 1;
        const int rbase = z * 16;
        const int m0 = rbase & ~127;
        const int zs4 = (g_foff[xb[m0]] & ~63) >> 2;
        const int ze4 = (min(NF, (g_foff[xb[m0 + 127] + 1] + 63) & ~63)) >> 2;
        const float4 zv = make_float4(0.f, 0.f, 0.f, 0.f);
        const int t = threadIdx.x;
#pragma unroll 1
        for (int rr = 0; rr < 16; rr++) {
            float4* p = (float4*)(attn + (size_t)(rbase + rr) * NF);
            for (int i = t; i < zs4; i += 256) p[i] = zv;
            for (int i = ze4 + t; i < (NF >> 2); i += 256) p[i] = zv;
        }
        return;
    }

    const int b = bidx >> 1;
    const int tid = threadIdx.x, lane = tid & 31, wid = tid >> 5, wm = wid >> 1, wn = wid & 1;

    const float *Ag, *Bg;
    __nv_bfloat16 *Coh, *Col;
    int lda, ldb, ldc, K, m0, n0;
    if (b < 128) {
        Ag = hI; lda = OUT_SIZE; K = OUT_SIZE;
        Bg = Wh; ldb = D_ATT; ldc = D_ATT;
        Coh = g_qh; Col = g_ql; m0 = (b >> 1) * 128; n0 = (b & 1) * 64;
    } else if (b < 256) {
        int lb = b - 128;
        Ag = fI; lda = F_SIZE; K = F_SIZE;
        Bg = Wk; ldb = D_ATT; ldc = D_ATT;
        Coh = g_kh; Col = g_kl; m0 = (lb >> 1) * 128; n0 = (lb & 1) * 64;
    } else {
        int lb = b - 256;
        Ag = fI; lda = F_SIZE; K = F_SIZE;
        Bg = Wv; ldb = OUT_SIZE; ldc = OUT_SIZE;
        Coh = g_vh; Col = g_vl; m0 = (lb >> 2) * 128; n0 = (lb & 3) * 64;
    }

    float4 areg[4], breg[2];
    auto ldgAB = [&](int k0) {
#pragma unroll
        for (int i = 0; i < 4; i++) {
            int idx = tid + i * 256, r = idx >> 3, c4 = (idx & 7) << 2;
            areg[i] = *(const float4*)(Ag + (size_t)(m0 + r) * lda + k0 + c4);
        }
#pragma unroll
        for (int i = 0; i < 2; i++) {
            int idx = tid + i * 256, r = idx >> 4, c4 = (idx & 15) << 2;
            breg[i] = *(const float4*)(Bg + (size_t)(k0 + r) * ldb + n0 + c4);
        }
    };
    auto stsAB = [&](int s) {
        __nv_bfloat16* bs = dsm + s * STG;
#pragma unroll
        for (int i = 0; i < 4; i++) {
            int idx = tid + i * 256, r = idx >> 3, c4 = (idx & 7) << 2;
            uint2 h_, l_; split4(areg[i], h_, l_);
            *(uint2*)(bs + r * 40 + c4) = h_;
            *(uint2*)(bs + AE + r * 40 + c4) = l_;
        }
#pragma unroll
        for (int i = 0; i < 2; i++) {
            int idx = tid + i * 256, r = idx >> 4, c4 = (idx & 15) << 2;
            uint2 h_, l_; split4(breg[i], h_, l_);
            *(uint2*)(bs + 2 * AE + r * 72 + c4) = h_;
            *(uint2*)(bs + 2 * AE + BE + r * 72 + c4) = l_;
        }
    };

    float acc[2][4][4] = {};
    const unsigned smB = su(dsm);

    auto compute = [&](int s) {
        unsigned aB = smB + 2 * (s * STG);
        unsigned alB = aB + 2 * AE;
        unsigned bB = aB + 2 * (2 * AE);
        unsigned blB = bB + 2 * BE;
#pragma unroll
        for (int ks = 0; ks < 32; ks += 16) {
            unsigned ah[2][4], al[2][4], bh[2][4], bl[2][4];
#pragma unroll
            for (int mf = 0; mf < 2; mf++) {
                unsigned off = 2u * ((wm * 32 + mf * 16 + (lane & 15)) * 40 + ks + ((lane >> 4) << 3));
                ldsm4(ah[mf], aB + off);
                ldsm4(al[mf], alB + off);
            }
#pragma unroll
            for (int p = 0; p < 2; p++) {
                unsigned off = 2u * ((ks + (lane & 15)) * 72 + wn * 32 + p * 16 + ((lane >> 4) << 3));
                ldsm4t(bh[p], bB + off);
                ldsm4t(bl[p], blB + off);
            }
#pragma unroll
            for (int mf = 0; mf < 2; mf++)
#pragma unroll
                for (int nf = 0; nf < 4; nf++) {
                    unsigned b0 = bh[nf >> 1][(nf & 1) * 2], b1 = bh[nf >> 1][(nf & 1) * 2 + 1];
                    unsigned c0 = bl[nf >> 1][(nf & 1) * 2], c1 = bl[nf >> 1][(nf & 1) * 2 + 1];
                    mma_bf(acc[mf][nf], ah[mf], b0, b1);
                    mma_bf(acc[mf][nf], al[mf], b0, b1);
                    mma_bf(acc[mf][nf], ah[mf], c0, c1);
                }
        }
    };

    const int nst = K / 32;
    ldgAB(0);
    stsAB(0);
    for (int t = 0; t < nst; t++) {
        int s = t & 1;
        bool more = (t + 1 < nst);
        if (more) ldgAB((t + 1) * 32);
        __syncthreads();
        compute(s);
        __syncthreads();
        if (more) stsAB(s ^ 1);
    }

#pragma unroll
    for (int mf = 0; mf < 2; mf++)
#pragma unroll
        for (int nf = 0; nf < 4; nf++) {
            int row = m0 + wm * 32 + mf * 16 + (lane >> 2);
            int col = n0 + wn * 32 + nf * 8 + ((lane & 3) << 1);
            unsigned h0, l0, h1, l1;
            split2w(acc[mf][nf][0], acc[mf][nf][1], h0, l0);
            split2w(acc[mf][nf][2], acc[mf][nf][3], h1, l1);
            *(unsigned*)(Coh + (size_t)row * ldc + col) = h0;
            *(unsigned*)(Col + (size_t)row * ldc + col) = l0;
            *(unsigned*)(Coh + (size_t)(row + 8) * ldc + col) = h1;
            *(unsigned*)(Col + (size_t)(row + 8) * ldc + col) = l1;
        }
}

// =====================================================================
// scores: R13 winner (unchanged).
// =====================================================================
#define QLD 136
#define QE (128 * QLD)
#define KE (64 * QLD)
#define SC_SMEM ((2 * QE + 2 * KE) * 2)

__global__ __launch_bounds__(256) void scores_tc(
    const int* __restrict__ xb, float* __restrict__ attn)
{
    extern __shared__ __align__(16) __nv_bfloat16 dsm[];
    __nv_bfloat16* Qh = dsm;
    __nv_bfloat16* Ql = Qh + QE;
    __nv_bfloat16* Kh = Ql + QE;
    __nv_bfloat16* Kl = Kh + KE;

    const int tid = threadIdx.x, lane = tid & 31, wid = tid >> 5, wm = wid >> 1, wn = wid & 1;
    const int m0 = blockIdx.y * 128;

    const int jmin = g_foff[xb[m0]];
    const int jmax = g_foff[xb[m0 + 127] + 1];
    const int jt_lo = jmin >> 6, jt_hi = (jmax + 63) >> 6;
    if (jt_lo + (int)blockIdx.x >= jt_hi) return;

    int fs[2][2], fe[2][2];
#pragma unroll
    for (int mf = 0; mf < 2; mf++)
#pragma unroll
        for (int hh = 0; hh < 2; hh++) {
            int row = m0 + wm * 32 + mf * 16 + (lane >> 2) + hh * 8;
            int g = xb[row];
            fs[mf][hh] = g_foff[g]; fe[mf][hh] = g_foff[g + 1];
        }

#pragma unroll
    for (int i = 0; i < 8; i++) {
        int idx = tid + i * 256, r = idx >> 4, c8 = (idx & 15) * 8;
        cpa16(Qh + r * QLD + c8, g_qh + (size_t)(m0 + r) * D_ATT + c8);
        cpa16(Ql + r * QLD + c8, g_ql + (size_t)(m0 + r) * D_ATT + c8);
    }
    CPA_COMMIT;

    const unsigned qhB = su(Qh), qlB = su(Ql), khB = su(Kh), klB = su(Kl);

    for (int jt = jt_lo + blockIdx.x; jt < jt_hi; jt += 8) {
        const int j0 = jt << 6;
#pragma unroll
        for (int i = 0; i < 4; i++) {
            int idx = tid + i * 256, r = idx >> 4, c8 = (idx & 15) * 8;
            cpa16(Kh + r * QLD + c8, g_kh + (size_t)(j0 + r) * D_ATT + c8);
            cpa16(Kl + r * QLD + c8, g_kl + (size_t)(j0 + r) * D_ATT + c8);
        }
        CPA_COMMIT;
        CPA_WAIT0;
        __syncthreads();

        float acc[2][4][4] = {};
#pragma unroll
        for (int d0 = 0; d0 < D_ATT; d0 += 16) {
            unsigned ah[2][4], al[2][4], bh[2][4], bl[2][4];
#pragma unroll
            for (int mf = 0; mf < 2; mf++) {
                unsigned off = 2u * ((wm * 32 + mf * 16 + (lane & 15)) * QLD + d0 + ((lane >> 4) << 3));
                ldsm4(ah[mf], qhB + off);
                ldsm4(al[mf], qlB + off);
            }
#pragma unroll
            for (int p = 0; p < 2; p++) {
                unsigned off = 2u * ((wn * 32 + p * 16 + ((lane >> 4) << 3) + (lane & 7)) * QLD + d0 + (lane & 8));
                ldsm4(bh[p], khB + off);
                ldsm4(bl[p], klB + off);
            }
#pragma unroll
            for (int mf = 0; mf < 2; mf++)
#pragma unroll
                for (int nf = 0; nf < 4; nf++) {
                    unsigned b0 = bh[nf >> 1][(nf & 1) * 2], b1 = bh[nf >> 1][(nf & 1) * 2 + 1];
                    unsigned c0 = bl[nf >> 1][(nf & 1) * 2], c1 = bl[nf >> 1][(nf & 1) * 2 + 1];
                    mma_bf(acc[mf][nf], ah[mf], b0, b1);
                    mma_bf(acc[mf][nf], al[mf], b0, b1);
                    mma_bf(acc[mf][nf], ah[mf], c0, c1);
                }
        }
        __syncthreads();

#pragma unroll
        for (int mf = 0; mf < 2; mf++) {
            int row = m0 + wm * 32 + mf * 16 + (lane >> 2);
#pragma unroll
            for (int nf = 0; nf < 4; nf++) {
                int col = j0 + wn * 32 + nf * 8 + ((lane & 3) << 1);
                float2 w0, w1;
                w0.x = (col >= fs[mf][0] && col < fe[mf][0])         ? acc[mf][nf][0] : 0.f;
                w0.y = (col + 1 >= fs[mf][0] && col + 1 < fe[mf][0]) ? acc[mf][nf][1] : 0.f;
                w1.x = (col >= fs[mf][1] && col < fe[mf][1])         ? acc[mf][nf][2] : 0.f;
                w1.y = (col + 1 >= fs[mf][1] && col + 1 < fe[mf][1]) ? acc[mf][nf][3] : 0.f;
                *(float2*)(attn + (size_t)row * NF + col) = w0;
                *(float2*)(attn + (size_t)(row + 8) * NF + col) = w1;
            }
        }
    }
}

// =====================================================================
// softmax: register-resident row (<=1024 band cols fast path),
// 1 read + 1 exp per element + 1 write. Spill path for larger bands.
// =====================================================================
__global__ __launch_bounds__(128) void softmax_kernel(
    float* __restrict__ attn, const int* __restrict__ xb)
{
    const int i = blockIdx.x, t = threadIdx.x;
    const int g = xb[i], fs = g_foff[g], fe = g_foff[g + 1];
    const int n = fe - fs;
    float* row = attn + (size_t)i * NF;
    __shared__ float redm[4], reds[4];

    float v[8];
    float m = -3.0e38f;
#pragma unroll
    for (int k = 0; k < 8; k++) {
        int j = fs + t + (k << 7);
        v[k] = (j < fe) ? row[j] : -3.0e38f;
        m = fmaxf(m, v[k]);
    }
    // spill tail (band > 1024): statistically never taken
    for (int j = fs + 1024 + t; j < fe; j += 128) m = fmaxf(m, row[j]);

#pragma unroll
    for (int o = 16; o; o >>= 1) m = fmaxf(m, __shfl_xor_sync(0xffffffffu, m, o));
    if ((t & 31) == 0) redm[t >> 5] = m;
    __syncthreads();
    const float mt = fmaxf(fmaxf(redm[0], redm[1]), fmaxf(redm[2], redm[3]));

    float e[8];
    float s = 0.f;
#pragma unroll
    for (int k = 0; k < 8; k++) {
        int j = fs + t + (k << 7);
        e[k] = (j < fe) ? __expf(v[k] - mt) : 0.f;
        s += e[k];
    }
    for (int j = fs + 1024 + t; j < fe; j += 128) s += __expf(row[j] - mt);

#pragma unroll
    for (int o = 16; o; o >>= 1) s += __shfl_xor_sync(0xffffffffu, s, o);
    if ((t & 31) == 0) reds[t >> 5] = s;
    __syncthreads();
    const float inv = 1.f / (reds[0] + reds[1] + reds[2] + reds[3]);

#pragma unroll
    for (int k = 0; k < 8; k++) {
        int j = fs + t + (k << 7);
        if (j < fe) row[j] = e[k] * inv;
    }
    for (int j = fs + 1024 + t; j < fe; j += 128) row[j] = __expf(row[j] - mt) * inv;

    (void)n;
}

// =====================================================================
// context: attn(band fp32) @ value(bf16 pre-split) (unchanged)
// =====================================================================
__global__ __launch_bounds__(256) void context_tc(
    const float* __restrict__ attn, float* __restrict__ ctx,
    const int* __restrict__ xb)
{
    extern __shared__ __align__(16) __nv_bfloat16 dsm[];
    const int tid = threadIdx.x, lane = tid & 31, wid = tid >> 5, wm = wid >> 1, wn = wid & 1;
    const int m0 = blockIdx.y * 128, n0 = blockIdx.x * 64;

    const int g0 = xb[m0], g1 = xb[m0 + 127];
    const int kbeg = g_foff[g0] & ~31;
    const int kend = g_foff[g1 + 1];
    const int nst = (kend - kbeg + 31) >> 5;

    float4 areg[4];
    auto ldgA = [&](int k0) {
#pragma unroll
        for (int i = 0; i < 4; i++) {
            int idx = tid + i * 256, r = idx >> 3, c4 = (idx & 7) << 2;
            areg[i] = *(const float4*)(attn + (size_t)(m0 + r) * NF + k0 + c4);
        }
    };
    auto stsA = [&](int s) {
        __nv_bfloat16* bs = dsm + s * STG;
#pragma unroll
        for (int i = 0; i < 4; i++) {
            int idx = tid + i * 256, r = idx >> 3, c4 = (idx & 7) << 2;
            uint2 h, l; split4(areg[i], h, l);
            *(uint2*)(bs + r * 40 + c4) = h;
            *(uint2*)(bs + AE + r * 40 + c4) = l;
        }
    };
    auto cpaB = [&](int k0, int s) {
        __nv_bfloat16* bs = dsm + s * STG + 2 * AE;
        int r = tid >> 3, c8 = (tid & 7) * 8;
        cpa16(bs + r * 72 + c8, g_vh + (size_t)(k0 + r) * OUT_SIZE + n0 + c8);
        cpa16(bs + BE + r * 72 + c8, g_vl + (size_t)(k0 + r) * OUT_SIZE + n0 + c8);
        CPA_COMMIT;
    };

    float acc[2][4][4] = {};
    const unsigned smB = su(dsm);

    auto compute = [&](int s) {
        unsigned aB = smB + 2 * (s * STG);
        unsigned alB = aB + 2 * AE;
        unsigned bB = aB + 2 * (2 * AE);
        unsigned blB = bB + 2 * BE;
#pragma unroll
        for (int ks = 0; ks < 32; ks += 16) {
            unsigned ah[2][4], al[2][4], bh[2][4], bl[2][4];
#pragma unroll
            for (int mf = 0; mf < 2; mf++) {
                unsigned off = 2u * ((wm * 32 + mf * 16 + (lane & 15)) * 40 + ks + ((lane >> 4) << 3));
                ldsm4(ah[mf], aB + off);
                ldsm4(al[mf], alB + off);
            }
#pragma unroll
            for (int p = 0; p < 2; p++) {
                unsigned off = 2u * ((ks + (lane & 15)) * 72 + wn * 32 + p * 16 + ((lane >> 4) << 3));
                ldsm4t(bh[p], bB + off);
                ldsm4t(bl[p], blB + off);
            }
#pragma unroll
            for (int mf = 0; mf < 2; mf++)
#pragma unroll
                for (int nf = 0; nf < 4; nf++) {
                    unsigned b0 = bh[nf >> 1][(nf & 1) * 2], b1 = bh[nf >> 1][(nf & 1) * 2 + 1];
                    unsigned c0 = bl[nf >> 1][(nf & 1) * 2], c1 = bl[nf >> 1][(nf & 1) * 2 + 1];
                    mma_bf(acc[mf][nf], ah[mf], b0, b1);
                    mma_bf(acc[mf][nf], al[mf], b0, b1);
                    mma_bf(acc[mf][nf], ah[mf], c0, c1);
                }
        }
    };

    ldgA(kbeg);
    stsA(0);
    cpaB(kbeg, 0);
    for (int t = 0; t < nst; t++) {
        int s = t & 1;
        bool more = (t + 1 < nst);
        if (more) { ldgA(kbeg + (t + 1) * 32); cpaB(kbeg + (t + 1) * 32, s ^ 1); CPA_WAIT1; }
        else { CPA_WAIT0; }
        __syncthreads();
        compute(s);
        __syncthreads();
        if (more) stsA(s ^ 1);
    }

#pragma unroll
    for (int mf = 0; mf < 2; mf++)
#pragma unroll
        for (int nf = 0; nf < 4; nf++) {
            int row = m0 + wm * 32 + mf * 16 + (lane >> 2);
            int col = n0 + wn * 32 + nf * 8 + ((lane & 3) << 1);
            *(float2*)(ctx + (size_t)row * OUT_SIZE + col) = make_float2(acc[mf][nf][0], acc[mf][nf][1]);
            *(float2*)(ctx + (size_t)(row + 8) * OUT_SIZE + col) = make_float2(acc[mf][nf][2], acc[mf][nf][3]);
        }
}

// ---------------- launch (single stream) ----------------
extern "C" void kernel_launch(void* const* d_in, const int* in_sizes, int n_in,
                              void* d_out, int out_size)
{
    const float* f       = (const float*)d_in[0];
    const float* h       = (const float*)d_in[2];
    const int*   f_batch = (const int*)  d_in[5];
    const int*   x_batch = (const int*)  d_in[6];
    const float* W_h     = (const float*)d_in[8];
    const float* W_key   = (const float*)d_in[9];
    const float* W_value = (const float*)d_in[10];

    float* out  = (float*)d_out;
    float* ctx  = out;
    float* attn = out + (size_t)NX * OUT_SIZE;

    cudaFuncSetAttribute(mega_tc,    cudaFuncAttributeMaxDynamicSharedMemorySize, MEGA_SMEM);
    cudaFuncSetAttribute(scores_tc,  cudaFuncAttributeMaxDynamicSharedMemorySize, SC_SMEM);
    cudaFuncSetAttribute(context_tc, cudaFuncAttributeMaxDynamicSharedMemorySize, CTX_SMEM);

    offsets_kernel<<<1, 32>>>(f_batch);
    mega_tc<<<1024, 256, MEGA_SMEM>>>(x_batch, attn, f, h, W_h, W_key, W_value);
    scores_tc<<<dim3(8, NX / 128), 256, SC_SMEM>>>(x_batch, attn);
    softmax_kernel<<<NX, 128>>>(attn, x_batch);
    context_tc<<<dim3(OUT_SIZE / 64, NX / 128), 256, CTX_SMEM>>>(attn, ctx, x_batch);
}